// round 1
// baseline (speedup 1.0000x reference)
#include <cuda_runtime.h>
#include <math.h>
#include <stdint.h>

// Problem constants
#define T_DIM 128
#define B_DIM 64
#define H_DIM 512
#define E_DIM 256
#define V_DIM 32000
#define VT_DIM (V_DIM + T_DIM)   // 32128
#define EPSC 1e-10f

// ---------------- scratch (single __device__ array, offsets in floats) ----------------
// energy  : (T*B) x H           4,194,304   (reused for copy GEMM output)
// hW1     : B x H                  32,768
// score   : B x T                   8,192   (alpha written in place)
// ctx     : B x H                  32,768
// x       : B x (E+H)              49,152
// gi      : B x 3H                 98,304
// gh      : B x 3H                 98,304
// hnew    : B x H                  32,768
// xp      : B x 2H                 65,536
// gen     : B x V               2,048,000
// raw     : B x T                   8,192
// scat    : B x (V+T)           2,056,192
// stats   : B x 8                     512
static constexpr size_t OFF_ENERGY = 0;
static constexpr size_t OFF_HW1    = OFF_ENERGY + (size_t)T_DIM * B_DIM * H_DIM;
static constexpr size_t OFF_SCORE  = OFF_HW1    + (size_t)B_DIM * H_DIM;
static constexpr size_t OFF_CTX    = OFF_SCORE  + (size_t)B_DIM * T_DIM;
static constexpr size_t OFF_X      = OFF_CTX    + (size_t)B_DIM * H_DIM;
static constexpr size_t OFF_GI     = OFF_X      + (size_t)B_DIM * (E_DIM + H_DIM);
static constexpr size_t OFF_GH     = OFF_GI     + (size_t)B_DIM * 3 * H_DIM;
static constexpr size_t OFF_HNEW   = OFF_GH     + (size_t)B_DIM * 3 * H_DIM;
static constexpr size_t OFF_XP     = OFF_HNEW   + (size_t)B_DIM * H_DIM;
static constexpr size_t OFF_GEN    = OFF_XP     + (size_t)B_DIM * 2 * H_DIM;
static constexpr size_t OFF_RAW    = OFF_GEN    + (size_t)B_DIM * V_DIM;
static constexpr size_t OFF_SCAT   = OFF_RAW    + (size_t)B_DIM * T_DIM;
static constexpr size_t OFF_STATS  = OFF_SCAT   + (size_t)B_DIM * VT_DIM;
static constexpr size_t SCRATCH_TOTAL = OFF_STATS + (size_t)B_DIM * 8;

__device__ float g_scratch[SCRATCH_TOTAL];

// ---------------- generic SGEMM:  C[m,n] = sum_k A[m,k] * B[n,k]  (B row-major [N,K]) ----------------
template<int BM, int BN, int BK, int TM, int TN>
__global__ void sgemm_tn(const float* __restrict__ A, const float* __restrict__ B,
                         float* __restrict__ C,
                         int M, int N, int K, int lda, int ldb, int ldc)
{
    constexpr int NTX = BN / TN;
    constexpr int NTY = BM / TM;
    constexpr int NT  = NTX * NTY;

    __shared__ float As[BK][BM + 4];
    __shared__ float Bs[BK][BN + 4];

    const int tid = threadIdx.x;
    const int tx  = tid % NTX;
    const int ty  = tid / NTX;
    const int m0  = blockIdx.y * BM;
    const int n0  = blockIdx.x * BN;

    float acc[TM][TN];
#pragma unroll
    for (int i = 0; i < TM; i++)
#pragma unroll
        for (int j = 0; j < TN; j++) acc[i][j] = 0.0f;

    for (int k0 = 0; k0 < K; k0 += BK) {
        // load A tile (BM x BK), store transposed As[k][m]
#pragma unroll
        for (int idx = tid; idx < BM * BK / 4; idx += NT) {
            int row = idx / (BK / 4);
            int c4  = idx % (BK / 4);
            float4 v = *(const float4*)&A[(size_t)(m0 + row) * lda + k0 + c4 * 4];
            As[c4 * 4 + 0][row] = v.x;
            As[c4 * 4 + 1][row] = v.y;
            As[c4 * 4 + 2][row] = v.z;
            As[c4 * 4 + 3][row] = v.w;
        }
        // load B tile (BN x BK), store transposed Bs[k][n]
#pragma unroll
        for (int idx = tid; idx < BN * BK / 4; idx += NT) {
            int row = idx / (BK / 4);
            int c4  = idx % (BK / 4);
            float4 v = *(const float4*)&B[(size_t)(n0 + row) * ldb + k0 + c4 * 4];
            Bs[c4 * 4 + 0][row] = v.x;
            Bs[c4 * 4 + 1][row] = v.y;
            Bs[c4 * 4 + 2][row] = v.z;
            Bs[c4 * 4 + 3][row] = v.w;
        }
        __syncthreads();

#pragma unroll
        for (int k = 0; k < BK; k++) {
            float ra[TM], rb[TN];
#pragma unroll
            for (int i = 0; i < TM; i += 4) {
                float4 v = *(const float4*)&As[k][ty * TM + i];
                ra[i] = v.x; ra[i + 1] = v.y; ra[i + 2] = v.z; ra[i + 3] = v.w;
            }
#pragma unroll
            for (int j = 0; j < TN; j += 4) {
                float4 v = *(const float4*)&Bs[k][tx * TN + j];
                rb[j] = v.x; rb[j + 1] = v.y; rb[j + 2] = v.z; rb[j + 3] = v.w;
            }
#pragma unroll
            for (int i = 0; i < TM; i++)
#pragma unroll
                for (int j = 0; j < TN; j++)
                    acc[i][j] += ra[i] * rb[j];
        }
        __syncthreads();
    }

    // epilogue
#pragma unroll
    for (int i = 0; i < TM; i++) {
        size_t row = (size_t)(m0 + ty * TM + i) * ldc + n0 + tx * TN;
#pragma unroll
        for (int j = 0; j < TN; j += 4) {
            float4 v;
            v.x = acc[i][j]; v.y = acc[i][j + 1]; v.z = acc[i][j + 2]; v.w = acc[i][j + 3];
            *(float4*)&C[row + j] = v;
        }
    }
}

// ---------------- elementwise / reduction kernels ----------------

__global__ void k_zero(float* p, int n)
{
    for (int i = blockIdx.x * blockDim.x + threadIdx.x; i < n; i += gridDim.x * blockDim.x)
        p[i] = 0.0f;
}

// score[b,t] = sum_h attn_v[h] * tanh(energy[(t*B+b),h] + hW1[b,h] + attn_b[h])
__global__ void k_score(const float* __restrict__ energy, const float* __restrict__ hW1,
                        const float* __restrict__ attn_b, const float* __restrict__ attn_v,
                        float* __restrict__ score)
{
    int warp = (blockIdx.x * blockDim.x + threadIdx.x) >> 5;
    int lane = threadIdx.x & 31;
    if (warp >= T_DIM * B_DIM) return;
    int b = warp % B_DIM;
    int t = warp / B_DIM;
    const float* e  = energy + (size_t)warp * H_DIM;
    const float* hw = hW1 + (size_t)b * H_DIM;
    float s = 0.0f;
    for (int h = lane; h < H_DIM; h += 32)
        s += attn_v[h] * tanhf(e[h] + hw[h] + attn_b[h]);
#pragma unroll
    for (int o = 16; o > 0; o >>= 1) s += __shfl_down_sync(0xffffffffu, s, o);
    if (lane == 0) score[b * T_DIM + t] = s;
}

// softmax over t per b, in place
__global__ void k_alpha(float* __restrict__ score)
{
    int b = blockIdx.x, t = threadIdx.x;
    __shared__ float sm[T_DIM];
    float v = score[b * T_DIM + t];
    sm[t] = v; __syncthreads();
    for (int o = 64; o > 0; o >>= 1) { if (t < o) sm[t] = fmaxf(sm[t], sm[t + o]); __syncthreads(); }
    float mx = sm[0]; __syncthreads();
    float e = expf(v - mx);
    sm[t] = e; __syncthreads();
    for (int o = 64; o > 0; o >>= 1) { if (t < o) sm[t] += sm[t + o]; __syncthreads(); }
    score[b * T_DIM + t] = e / sm[0];
}

// ctx[b,h] = sum_t alpha[b,t] * u_enc_out[t,b,h]
__global__ void k_ctx(const float* __restrict__ alpha, const float* __restrict__ enc,
                      float* __restrict__ ctx)
{
    int b = blockIdx.x, h = threadIdx.x;
    __shared__ float al[T_DIM];
    if (h < T_DIM) al[h] = alpha[b * T_DIM + h];
    __syncthreads();
    float acc = 0.0f;
    for (int t = 0; t < T_DIM; t++)
        acc += al[t] * enc[((size_t)t * B_DIM + b) * H_DIM + h];
    ctx[b * H_DIM + h] = acc;
}

// x[b] = [emb[z[b]] (E), ctx[b] (H)]
__global__ void k_build_x(const int* __restrict__ z, const float* __restrict__ emb,
                          const float* __restrict__ ctx, float* __restrict__ x)
{
    int i = blockIdx.x * blockDim.x + threadIdx.x;
    if (i >= B_DIM * (E_DIM + H_DIM)) return;
    int b = i / (E_DIM + H_DIM);
    int c = i % (E_DIM + H_DIM);
    x[i] = (c < E_DIM) ? emb[(size_t)z[b] * E_DIM + c]
                       : ctx[b * H_DIM + (c - E_DIM)];
}

// GRU gates + write gru_out/new_hidden + build xp = [h_new, ctx]
__global__ void k_gru(const float* __restrict__ gi, const float* __restrict__ gh,
                      const float* __restrict__ bih, const float* __restrict__ bhh,
                      const float* __restrict__ h_prev, const float* __restrict__ ctx,
                      float* __restrict__ hnew, float* __restrict__ xp,
                      float* __restrict__ out)
{
    int b = blockIdx.x, h = threadIdx.x;
    const float* gib = gi + (size_t)b * 3 * H_DIM;
    const float* ghb = gh + (size_t)b * 3 * H_DIM;
    float ir = gib[h]              + bih[h];
    float iz = gib[H_DIM + h]      + bih[H_DIM + h];
    float in_ = gib[2 * H_DIM + h] + bih[2 * H_DIM + h];
    float hr = ghb[h]              + bhh[h];
    float hz = ghb[H_DIM + h]      + bhh[H_DIM + h];
    float hn = ghb[2 * H_DIM + h]  + bhh[2 * H_DIM + h];
    float r  = 1.0f / (1.0f + expf(-(ir + hr)));
    float zz = 1.0f / (1.0f + expf(-(iz + hz)));
    float n  = tanhf(in_ + r * hn);
    float hp = h_prev[b * H_DIM + h];
    float v  = (1.0f - zz) * n + zz * hp;
    hnew[b * H_DIM + h] = v;
    out[b * H_DIM + h] = v;                       // gru_out
    out[B_DIM * H_DIM + b * H_DIM + h] = v;       // new_hidden
    xp[b * 2 * H_DIM + h] = v;
    xp[b * 2 * H_DIM + H_DIM + h] = ctx[b * H_DIM + h];
}

// raw[b,t] = sum_h tanh(encC[(t*B+b),h] + copy1_b[h]) * hnew[b,h]
__global__ void k_raw(const float* __restrict__ encC, const float* __restrict__ c1b,
                      const float* __restrict__ hnew, float* __restrict__ raw)
{
    int warp = (blockIdx.x * blockDim.x + threadIdx.x) >> 5;
    int lane = threadIdx.x & 31;
    if (warp >= T_DIM * B_DIM) return;
    int b = warp % B_DIM;
    int t = warp / B_DIM;
    const float* e  = encC + (size_t)warp * H_DIM;
    const float* hn = hnew + (size_t)b * H_DIM;
    float s = 0.0f;
    for (int h = lane; h < H_DIM; h += 32)
        s += tanhf(e[h] + c1b[h]) * hn[h];
#pragma unroll
    for (int o = 16; o > 0; o >>= 1) s += __shfl_down_sync(0xffffffffu, s, o);
    if (lane == 0) raw[b * T_DIM + t] = s;
}

// per-b: cmax, total, sum(ex*mask), deterministic scatter into dense scat, scat_max
__global__ void k_copystats(const float* __restrict__ raw, const int* __restrict__ u_input,
                            float* __restrict__ scat, float* __restrict__ stats)
{
    int b = blockIdx.x, t = threadIdx.x;
    __shared__ float sm[T_DIM];
    __shared__ float exm[T_DIM];
    __shared__ int   sidx[T_DIM];
    float v = raw[b * T_DIM + t];
    sm[t] = v; __syncthreads();
    for (int o = 64; o > 0; o >>= 1) { if (t < o) sm[t] = fmaxf(sm[t], sm[t + o]); __syncthreads(); }
    float cmax = sm[0]; __syncthreads();

    float e = expf(v - cmax);
    int tok = u_input[t * B_DIM + b];
    sidx[t] = (tok == 2) ? (V_DIM + t) : tok;
    exm[t]  = (tok != 0) ? e : 0.0f;

    sm[t] = e; __syncthreads();
    for (int o = 64; o > 0; o >>= 1) { if (t < o) sm[t] += sm[t + o]; __syncthreads(); }
    float total = sm[0]; __syncthreads();

    sm[t] = exm[t]; __syncthreads();
    for (int o = 64; o > 0; o >>= 1) { if (t < o) sm[t] += sm[t + o]; __syncthreads(); }
    float sum_exm = sm[0]; __syncthreads();

    if (t == 0) {
        float* sc = scat + (size_t)b * VT_DIM;
        for (int i = 0; i < T_DIM; i++) sc[sidx[i]] += exm[i];   // deterministic scatter
        float smax = 0.0f;                                       // unscattered entries are 0
        for (int i = 0; i < T_DIM; i++) smax = fmaxf(smax, sc[sidx[i]]);
        stats[b * 8 + 0] = cmax;
        stats[b * 8 + 1] = total;
        stats[b * 8 + 2] = sum_exm;
        stats[b * 8 + 3] = smax;
    }
}

// per-b online max/sum over gen (+proj_b), combine analytically with u_copy side
__global__ void k_reduce(const float* __restrict__ gen, const float* __restrict__ projb,
                         float* __restrict__ stats)
{
    int b = blockIdx.x, tid = threadIdx.x;
    float m = -1e30f, s = 0.0f;
    for (int v = tid; v < V_DIM; v += 256) {
        float l = gen[(size_t)b * V_DIM + v] + projb[v];
        float mn = fmaxf(m, l);
        s = s * expf(m - mn) + expf(l - mn);
        m = mn;
    }
    __shared__ float ms[256], ss[256];
    ms[tid] = m; ss[tid] = s; __syncthreads();
    for (int o = 128; o > 0; o >>= 1) {
        if (tid < o) {
            float m2 = ms[tid + o], s2 = ss[tid + o];
            float mn = fmaxf(ms[tid], m2);
            ss[tid] = ss[tid] * expf(ms[tid] - mn) + s2 * expf(m2 - mn);
            ms[tid] = mn;
        }
        __syncthreads();
    }
    if (tid == 0) {
        float cmax = stats[b * 8 + 0];
        float total = stats[b * 8 + 1];
        float sum_exm = stats[b * 8 + 2];
        float smax = stats[b * 8 + 3];
        float mg = ms[0], sg = ss[0];
        float mc = logf(EPSC * total + (1.0f - EPSC) * smax) + cmax;
        float M = fmaxf(mg, mc);
        float A = expf(cmax - M);
        float S = sg * expf(mg - M)
                + A * (EPSC * total * (float)VT_DIM + (1.0f - EPSC) * sum_exm);
        stats[b * 8 + 4] = M;
        stats[b * 8 + 5] = S;
        stats[b * 8 + 6] = A;
    }
}

// proba[b,j] = [j<V: exp(gen+pb-M)/S] + A*(EPS*total + (1-EPS)*scat[b,j]) / S
__global__ void k_final(const float* __restrict__ gen, const float* __restrict__ projb,
                        const float* __restrict__ scat, const float* __restrict__ stats,
                        float* __restrict__ out)
{
    int i = blockIdx.x * blockDim.x + threadIdx.x;
    if (i >= B_DIM * VT_DIM) return;
    int b = i / VT_DIM;
    int j = i % VT_DIM;
    float M = stats[b * 8 + 4];
    float S = stats[b * 8 + 5];
    float A = stats[b * 8 + 6];
    float total = stats[b * 8 + 1];
    float val = A * (EPSC * total + (1.0f - EPSC) * scat[i]) / S;
    if (j < V_DIM)
        val += expf(gen[(size_t)b * V_DIM + j] + projb[j] - M) / S;
    out[2 * B_DIM * H_DIM + i] = val;
}

// ---------------- host launcher ----------------
extern "C" void kernel_launch(void* const* d_in, const int* in_sizes, int n_in,
                              void* d_out, int out_size)
{
    const float* u_enc  = (const float*)d_in[0];
    const int*   z_tm1  = (const int*)  d_in[1];
    const float* h0     = (const float*)d_in[2];
    const int*   u_inp  = (const int*)  d_in[3];
    const float* emb    = (const float*)d_in[4];
    const float* attn_W = (const float*)d_in[5];
    const float* attn_b = (const float*)d_in[6];
    const float* attn_v = (const float*)d_in[7];
    const float* gWih   = (const float*)d_in[8];
    const float* gWhh   = (const float*)d_in[9];
    const float* gbih   = (const float*)d_in[10];
    const float* gbhh   = (const float*)d_in[11];
    const float* projW  = (const float*)d_in[12];
    const float* projb  = (const float*)d_in[13];
    const float* c1W    = (const float*)d_in[14];
    const float* c1b    = (const float*)d_in[15];
    float* out = (float*)d_out;

    float* base = nullptr;
    cudaGetSymbolAddress((void**)&base, g_scratch);
    float* energy = base + OFF_ENERGY;
    float* hW1    = base + OFF_HW1;
    float* score  = base + OFF_SCORE;
    float* ctx    = base + OFF_CTX;
    float* x      = base + OFF_X;
    float* gi     = base + OFF_GI;
    float* gh     = base + OFF_GH;
    float* hnew   = base + OFF_HNEW;
    float* xp     = base + OFF_XP;
    float* gen    = base + OFF_GEN;
    float* raw    = base + OFF_RAW;
    float* scat   = base + OFF_SCAT;
    float* stats  = base + OFF_STATS;

    const int MROWS = T_DIM * B_DIM;  // 8192

    // 0) zero the dense scatter buffer
    k_zero<<<512, 256>>>(scat, B_DIM * VT_DIM);

    // 1) hW1 = h @ W1^T   (W1 = attn_W[:, :H], row stride 2H)
    sgemm_tn<64, 128, 16, 8, 8><<<dim3(H_DIM / 128, 1), 128>>>(
        h0, attn_W, hW1, B_DIM, H_DIM, H_DIM, H_DIM, 2 * H_DIM, H_DIM);

    // 2) energy_pre = enc_rows @ W2^T   (W2 = attn_W[:, H:], offset H, stride 2H)
    sgemm_tn<128, 128, 16, 8, 8><<<dim3(H_DIM / 128, MROWS / 128), 256>>>(
        u_enc, attn_W + H_DIM, energy, MROWS, H_DIM, H_DIM, H_DIM, 2 * H_DIM, H_DIM);

    // 3) attention score, softmax, context
    k_score<<<MROWS / 8, 256>>>(energy, hW1, attn_b, attn_v, score);
    k_alpha<<<B_DIM, T_DIM>>>(score);
    k_ctx<<<B_DIM, H_DIM>>>(score, u_enc, ctx);

    // 4) GRU input x = [emb[z], ctx]; gi, gh GEMMs; gate fusion
    k_build_x<<<(B_DIM * (E_DIM + H_DIM) + 255) / 256, 256>>>(z_tm1, emb, ctx, x);
    sgemm_tn<64, 128, 16, 8, 8><<<dim3(3 * H_DIM / 128, 1), 128>>>(
        x, gWih, gi, B_DIM, 3 * H_DIM, E_DIM + H_DIM, E_DIM + H_DIM, E_DIM + H_DIM, 3 * H_DIM);
    sgemm_tn<64, 128, 16, 8, 8><<<dim3(3 * H_DIM / 128, 1), 128>>>(
        h0, gWhh, gh, B_DIM, 3 * H_DIM, H_DIM, H_DIM, H_DIM, 3 * H_DIM);
    k_gru<<<B_DIM, H_DIM>>>(gi, gh, gbih, gbhh, h0, ctx, hnew, xp, out);

    // 5) gen_score = [h_new, ctx] @ proj_W^T
    sgemm_tn<64, 128, 16, 8, 8><<<dim3(V_DIM / 128, 1), 128>>>(
        xp, projW, gen, B_DIM, V_DIM, 2 * H_DIM, 2 * H_DIM, 2 * H_DIM, V_DIM);

    // 6) copy scores: encC = enc_rows @ copy1_W^T (reuse energy scratch), raw dot h_new
    sgemm_tn<128, 128, 16, 8, 8><<<dim3(H_DIM / 128, MROWS / 128), 256>>>(
        u_enc, c1W, energy, MROWS, H_DIM, H_DIM, H_DIM, H_DIM, H_DIM);
    k_raw<<<MROWS / 8, 256>>>(energy, c1b, hnew, raw);

    // 7) copy log-score stats + deterministic scatter
    k_copystats<<<B_DIM, T_DIM>>>(raw, u_inp, scat, stats);

    // 8) global softmax reduction over [gen | u_copy] (u_copy folded analytically)
    k_reduce<<<B_DIM, 256>>>(gen, projb, stats);

    // 9) final proba
    k_final<<<(B_DIM * VT_DIM + 255) / 256, 256>>>(gen, projb, scat, stats, out);
}

// round 3
// speedup vs baseline: 2.8291x; 2.8291x over previous
#include <cuda_runtime.h>
#include <cuda_bf16.h>
#include <math.h>
#include <stdint.h>

// Problem constants
#define T_DIM 128
#define B_DIM 64
#define H_DIM 512
#define E_DIM 256
#define V_DIM 32000
#define VT_DIM (V_DIM + T_DIM)   // 32128
#define EPSC 1e-10f

// ---------------- scratch ----------------
static constexpr size_t OFF_ENERGY = 0;
static constexpr size_t OFF_HW1    = OFF_ENERGY + (size_t)T_DIM * B_DIM * H_DIM;
static constexpr size_t OFF_SCORE  = OFF_HW1    + (size_t)B_DIM * H_DIM;
static constexpr size_t OFF_CTX    = OFF_SCORE  + (size_t)B_DIM * T_DIM;
static constexpr size_t OFF_X      = OFF_CTX    + (size_t)B_DIM * H_DIM;
static constexpr size_t OFF_GI     = OFF_X      + (size_t)B_DIM * (E_DIM + H_DIM);
static constexpr size_t OFF_GH     = OFF_GI     + (size_t)B_DIM * 3 * H_DIM;
static constexpr size_t OFF_HNEW   = OFF_GH     + (size_t)B_DIM * 3 * H_DIM;
static constexpr size_t OFF_XP     = OFF_HNEW   + (size_t)B_DIM * H_DIM;
static constexpr size_t OFF_GEN    = OFF_XP     + (size_t)B_DIM * 2 * H_DIM;
static constexpr size_t OFF_RAW    = OFF_GEN    + (size_t)B_DIM * V_DIM;
static constexpr size_t OFF_SCAT   = OFF_RAW    + (size_t)B_DIM * T_DIM;
static constexpr size_t OFF_STATS  = OFF_SCAT   + (size_t)B_DIM * VT_DIM;
static constexpr size_t SCRATCH_TOTAL = OFF_STATS + (size_t)B_DIM * 8;

__device__ __align__(16) float g_scratch[SCRATCH_TOTAL];

// ================= warp MMA helpers (baseline PTX, sm_80+ — no arch-suffix needed) ====
__device__ __forceinline__ uint32_t smem_u32(const void* p) {
    uint32_t a;
    asm("{ .reg .u64 t; cvta.to.shared.u64 t, %1; cvt.u32.u64 %0, t; }" : "=r"(a) : "l"(p));
    return a;
}
__device__ __forceinline__ void ldsm4(uint32_t* r, uint32_t addr) {
    asm volatile("ldmatrix.sync.aligned.m8n8.x4.shared.b16 {%0,%1,%2,%3}, [%4];"
        : "=r"(r[0]), "=r"(r[1]), "=r"(r[2]), "=r"(r[3]) : "r"(addr));
}
__device__ __forceinline__ void mma_bf16(float* c, const uint32_t* a, const uint32_t* b) {
    asm volatile("mma.sync.aligned.m16n8k16.row.col.f32.bf16.bf16.f32 "
        "{%0,%1,%2,%3}, {%4,%5,%6,%7}, {%8,%9}, {%0,%1,%2,%3};"
        : "+f"(c[0]), "+f"(c[1]), "+f"(c[2]), "+f"(c[3])
        : "r"(a[0]), "r"(a[1]), "r"(a[2]), "r"(a[3]), "r"(b[0]), "r"(b[1]));
}
// fp32 -> (bf16 hi rn, bf16 lo rn) packed pairs for a float4
__device__ __forceinline__ void cvt_split(float4 v, uint2& hi, uint2& lo) {
    uint32_t h01, h23;
    asm("cvt.rn.bf16x2.f32 %0, %1, %2;" : "=r"(h01) : "f"(v.y), "f"(v.x));
    asm("cvt.rn.bf16x2.f32 %0, %1, %2;" : "=r"(h23) : "f"(v.w), "f"(v.z));
    float h0 = __uint_as_float(h01 << 16);
    float h1 = __uint_as_float(h01 & 0xffff0000u);
    float h2 = __uint_as_float(h23 << 16);
    float h3 = __uint_as_float(h23 & 0xffff0000u);
    uint32_t l01, l23;
    asm("cvt.rn.bf16x2.f32 %0, %1, %2;" : "=r"(l01) : "f"(v.y - h1), "f"(v.x - h0));
    asm("cvt.rn.bf16x2.f32 %0, %1, %2;" : "=r"(l23) : "f"(v.w - h3), "f"(v.z - h2));
    hi = make_uint2(h01, h23);
    lo = make_uint2(l01, l23);
}

// ================= tensor-core GEMM (HMMA, bf16x3 split) =================
// C[m,n] = sum_k A[m,k] * B[n,k]; fp32 in/out. Tile 128x128, BK=32, 256 threads.
// smem per stage: A_hi,A_lo,B_hi,B_lo each 128 rows x 32 bf16, row stride 80B = 10240B.
static constexpr int ROWB   = 80;                 // bytes per smem row (32 bf16 + pad)
static constexpr int TILEB  = 128 * ROWB;         // 10240
static constexpr int STAGEB = 4 * TILEB;          // 40960
static constexpr int TG_SMEM = 2 * STAGEB;        // 81920

__global__ void __launch_bounds__(256, 1) tgemm(
    const float* __restrict__ A, const float* __restrict__ B, float* __restrict__ C,
    int M_A, int M_C, int K, int lda, int ldb, int ldc)
{
    extern __shared__ char smem[];
    const uint32_t sb = smem_u32(smem);
    const int tid  = threadIdx.x;
    const int lane = tid & 31;
    const int warp = tid >> 5;
    const int wy   = warp >> 2;      // 0..1  (M half)
    const int wx   = warp & 3;       // 0..3  (N quarter)
    const int m0   = blockIdx.y * 128;
    const int n0   = blockIdx.x * 128;

    float acc[4][4][4];
#pragma unroll
    for (int i = 0; i < 4; i++)
#pragma unroll
        for (int j = 0; j < 4; j++)
#pragma unroll
            for (int q = 0; q < 4; q++) acc[i][j][q] = 0.0f;

    const int nchunk = K >> 5;
    float4 ra[4], rb[4];

    // ---- helpers as lambdas ----
    auto load_regs = [&](int c) {
        const int k0 = c << 5;
#pragma unroll
        for (int i = 0; i < 4; i++) {
            int id  = tid + (i << 8);
            int row = id >> 3;
            int kq  = id & 7;
            ra[i] = (m0 + row < M_A)
                  ? *(const float4*)&A[(size_t)(m0 + row) * lda + k0 + (kq << 2)]
                  : make_float4(0.f, 0.f, 0.f, 0.f);
            rb[i] = *(const float4*)&B[(size_t)(n0 + row) * ldb + k0 + (kq << 2)];
        }
    };
    auto store_smem = [&](int stage) {
        char* base = smem + stage * STAGEB;
#pragma unroll
        for (int i = 0; i < 4; i++) {
            int id  = tid + (i << 8);
            int row = id >> 3;
            int kq  = id & 7;
            int off = row * ROWB + (kq << 3);
            uint2 hi, lo;
            cvt_split(ra[i], hi, lo);
            *(uint2*)(base + off)          = hi;   // A_hi
            *(uint2*)(base + TILEB + off)  = lo;   // A_lo
            cvt_split(rb[i], hi, lo);
            *(uint2*)(base + 2 * TILEB + off) = hi; // B_hi
            *(uint2*)(base + 3 * TILEB + off) = lo; // B_lo
        }
    };
    auto compute = [&](int stage) {
        const uint32_t s0 = sb + stage * STAGEB;
        const int q = lane >> 3, r = lane & 7;
#pragma unroll
        for (int ks = 0; ks < 32; ks += 16) {
            uint32_t a_hi[4][4], a_lo[4][4], b_hi[4][2], b_lo[4][2];
            // A fragments: rows wy*64 + mt*16 + ((q&1)?8:0)+r, cols ks + ((q&2)?8:0)
            {
                int arow = wy * 64 + ((q & 1) ? 8 : 0) + r;
                int acol = ks + ((q & 2) ? 8 : 0);
                uint32_t addr = s0 + arow * ROWB + acol * 2;
#pragma unroll
                for (int mt = 0; mt < 4; mt++) {
                    ldsm4(a_hi[mt], addr + mt * (16 * ROWB));
                    ldsm4(a_lo[mt], addr + TILEB + mt * (16 * ROWB));
                }
            }
            // B fragments: rows wx*32 + np*16 + ((q&2)?8:0)+r, cols ks + ((q&1)?8:0)
            {
                int brow = wx * 32 + ((q & 2) ? 8 : 0) + r;
                int bcol = ks + ((q & 1) ? 8 : 0);
                uint32_t addr = s0 + 2 * TILEB + brow * ROWB + bcol * 2;
#pragma unroll
                for (int np = 0; np < 2; np++) {
                    ldsm4(&b_hi[np * 2][0], addr + np * (16 * ROWB));
                    ldsm4(&b_lo[np * 2][0], addr + TILEB + np * (16 * ROWB));
                }
            }
#pragma unroll
            for (int mt = 0; mt < 4; mt++)
#pragma unroll
                for (int nt = 0; nt < 4; nt++) {
                    mma_bf16(acc[mt][nt], a_hi[mt], b_hi[nt]);
                    mma_bf16(acc[mt][nt], a_hi[mt], b_lo[nt]);
                    mma_bf16(acc[mt][nt], a_lo[mt], b_hi[nt]);
                }
        }
    };

    // ---- pipelined main loop ----
    load_regs(0);
    store_smem(0);
    if (nchunk > 1) load_regs(1);
    __syncthreads();
    for (int c = 0; c < nchunk; c++) {
        if (c + 1 < nchunk) store_smem((c + 1) & 1);
        if (c + 2 < nchunk) load_regs(c + 2);
        compute(c & 1);
        __syncthreads();
    }

    // ---- epilogue ----
    const int g = lane >> 2, tig = lane & 3;
#pragma unroll
    for (int mt = 0; mt < 4; mt++) {
        int row0 = m0 + wy * 64 + mt * 16 + g;
#pragma unroll
        for (int nt = 0; nt < 4; nt++) {
            int col = n0 + wx * 32 + nt * 8 + tig * 2;
            if (row0 < M_C) {
                *(float2*)&C[(size_t)row0 * ldc + col] = make_float2(acc[mt][nt][0], acc[mt][nt][1]);
                *(float2*)&C[(size_t)(row0 + 8) * ldc + col] = make_float2(acc[mt][nt][2], acc[mt][nt][3]);
            }
        }
    }
}

// ================= elementwise / reduction kernels =================

__global__ void k_zero(float* p, int n)
{
    for (int i = blockIdx.x * blockDim.x + threadIdx.x; i < n; i += gridDim.x * blockDim.x)
        p[i] = 0.0f;
}

__global__ void k_score(const float* __restrict__ energy, const float* __restrict__ hW1,
                        const float* __restrict__ attn_b, const float* __restrict__ attn_v,
                        float* __restrict__ score)
{
    int warp = (blockIdx.x * blockDim.x + threadIdx.x) >> 5;
    int lane = threadIdx.x & 31;
    if (warp >= T_DIM * B_DIM) return;
    int b = warp % B_DIM;
    const float* e  = energy + (size_t)warp * H_DIM;
    const float* hw = hW1 + (size_t)b * H_DIM;
    float s = 0.0f;
    for (int h = lane; h < H_DIM; h += 32)
        s += attn_v[h] * tanhf(e[h] + hw[h] + attn_b[h]);
#pragma unroll
    for (int o = 16; o > 0; o >>= 1) s += __shfl_down_sync(0xffffffffu, s, o);
    if (lane == 0) score[b * T_DIM + (warp / B_DIM)] = s;
}

__global__ void k_alpha(float* __restrict__ score)
{
    int b = blockIdx.x, t = threadIdx.x;
    __shared__ float sm[T_DIM];
    float v = score[b * T_DIM + t];
    sm[t] = v; __syncthreads();
    for (int o = 64; o > 0; o >>= 1) { if (t < o) sm[t] = fmaxf(sm[t], sm[t + o]); __syncthreads(); }
    float mx = sm[0]; __syncthreads();
    float e = expf(v - mx);
    sm[t] = e; __syncthreads();
    for (int o = 64; o > 0; o >>= 1) { if (t < o) sm[t] += sm[t + o]; __syncthreads(); }
    score[b * T_DIM + t] = e / sm[0];
}

__global__ void k_ctx(const float* __restrict__ alpha, const float* __restrict__ enc,
                      float* __restrict__ ctx)
{
    int b = blockIdx.x, h = threadIdx.x;
    __shared__ float al[T_DIM];
    if (h < T_DIM) al[h] = alpha[b * T_DIM + h];
    __syncthreads();
    float acc = 0.0f;
    for (int t = 0; t < T_DIM; t++)
        acc += al[t] * enc[((size_t)t * B_DIM + b) * H_DIM + h];
    ctx[b * H_DIM + h] = acc;
}

__global__ void k_build_x(const int* __restrict__ z, const float* __restrict__ emb,
                          const float* __restrict__ ctx, float* __restrict__ x)
{
    int i = blockIdx.x * blockDim.x + threadIdx.x;
    if (i >= B_DIM * (E_DIM + H_DIM)) return;
    int b = i / (E_DIM + H_DIM);
    int c = i % (E_DIM + H_DIM);
    x[i] = (c < E_DIM) ? emb[(size_t)z[b] * E_DIM + c] : ctx[b * H_DIM + (c - E_DIM)];
}

__global__ void k_gru(const float* __restrict__ gi, const float* __restrict__ gh,
                      const float* __restrict__ bih, const float* __restrict__ bhh,
                      const float* __restrict__ h_prev, const float* __restrict__ ctx,
                      float* __restrict__ hnew, float* __restrict__ xp,
                      float* __restrict__ out)
{
    int b = blockIdx.x, h = threadIdx.x;
    const float* gib = gi + (size_t)b * 3 * H_DIM;
    const float* ghb = gh + (size_t)b * 3 * H_DIM;
    float ir  = gib[h]              + bih[h];
    float iz  = gib[H_DIM + h]      + bih[H_DIM + h];
    float in_ = gib[2 * H_DIM + h]  + bih[2 * H_DIM + h];
    float hr  = ghb[h]              + bhh[h];
    float hz  = ghb[H_DIM + h]      + bhh[H_DIM + h];
    float hn  = ghb[2 * H_DIM + h]  + bhh[2 * H_DIM + h];
    float r  = 1.0f / (1.0f + expf(-(ir + hr)));
    float zz = 1.0f / (1.0f + expf(-(iz + hz)));
    float n  = tanhf(in_ + r * hn);
    float hp = h_prev[b * H_DIM + h];
    float v  = (1.0f - zz) * n + zz * hp;
    hnew[b * H_DIM + h] = v;
    out[b * H_DIM + h] = v;
    out[B_DIM * H_DIM + b * H_DIM + h] = v;
    xp[b * 2 * H_DIM + h] = v;
    xp[b * 2 * H_DIM + H_DIM + h] = ctx[b * H_DIM + h];
}

__global__ void k_raw(const float* __restrict__ encC, const float* __restrict__ c1b,
                      const float* __restrict__ hnew, float* __restrict__ raw)
{
    int warp = (blockIdx.x * blockDim.x + threadIdx.x) >> 5;
    int lane = threadIdx.x & 31;
    if (warp >= T_DIM * B_DIM) return;
    int b = warp % B_DIM;
    const float* e  = encC + (size_t)warp * H_DIM;
    const float* hn = hnew + (size_t)b * H_DIM;
    float s = 0.0f;
    for (int h = lane; h < H_DIM; h += 32)
        s += tanhf(e[h] + c1b[h]) * hn[h];
#pragma unroll
    for (int o = 16; o > 0; o >>= 1) s += __shfl_down_sync(0xffffffffu, s, o);
    if (lane == 0) raw[b * T_DIM + (warp / B_DIM)] = s;
}

// parallel deterministic scatter (ascending-t accumulation == serial order)
__global__ void k_copystats(const float* __restrict__ raw, const int* __restrict__ u_input,
                            float* __restrict__ scat, float* __restrict__ stats)
{
    int b = blockIdx.x, t = threadIdx.x;
    __shared__ float sm[T_DIM];
    __shared__ float exm[T_DIM];
    __shared__ int   sidx[T_DIM];
    float v = raw[b * T_DIM + t];
    sm[t] = v; __syncthreads();
    for (int o = 64; o > 0; o >>= 1) { if (t < o) sm[t] = fmaxf(sm[t], sm[t + o]); __syncthreads(); }
    float cmax = sm[0]; __syncthreads();

    float e = expf(v - cmax);
    int tok = u_input[t * B_DIM + b];
    sidx[t] = (tok == 2) ? (V_DIM + t) : tok;
    float em = (tok != 0) ? e : 0.0f;
    exm[t] = em;

    sm[t] = e; __syncthreads();
    for (int o = 64; o > 0; o >>= 1) { if (t < o) sm[t] += sm[t + o]; __syncthreads(); }
    float total = sm[0]; __syncthreads();

    sm[t] = em; __syncthreads();
    for (int o = 64; o > 0; o >>= 1) { if (t < o) sm[t] += sm[t + o]; __syncthreads(); }
    float sum_exm = sm[0]; __syncthreads();

    int idx = sidx[t];
    bool first = true;
    for (int i = 0; i < t; i++) if (sidx[i] == idx) { first = false; break; }
    float a = 0.0f;
    if (first) {
        for (int i = t; i < T_DIM; i++) if (sidx[i] == idx) a += exm[i];
        scat[(size_t)b * VT_DIM + idx] = a;
    }
    sm[t] = a; __syncthreads();
    for (int o = 64; o > 0; o >>= 1) { if (t < o) sm[t] = fmaxf(sm[t], sm[t + o]); __syncthreads(); }
    if (t == 0) {
        stats[b * 8 + 0] = cmax;
        stats[b * 8 + 1] = total;
        stats[b * 8 + 2] = sum_exm;
        stats[b * 8 + 3] = sm[0];
    }
}

__global__ void k_reduce(const float* __restrict__ gen, const float* __restrict__ projb,
                         float* __restrict__ stats)
{
    int b = blockIdx.x, tid = threadIdx.x;
    float m = -1e30f, s = 0.0f;
    for (int v = tid; v < V_DIM; v += 256) {
        float l = gen[(size_t)b * V_DIM + v] + projb[v];
        float mn = fmaxf(m, l);
        s = s * expf(m - mn) + expf(l - mn);
        m = mn;
    }
    __shared__ float ms[256], ss[256];
    ms[tid] = m; ss[tid] = s; __syncthreads();
    for (int o = 128; o > 0; o >>= 1) {
        if (tid < o) {
            float m2 = ms[tid + o], s2 = ss[tid + o];
            float mn = fmaxf(ms[tid], m2);
            ss[tid] = ss[tid] * expf(ms[tid] - mn) + s2 * expf(m2 - mn);
            ms[tid] = mn;
        }
        __syncthreads();
    }
    if (tid == 0) {
        float cmax = stats[b * 8 + 0];
        float total = stats[b * 8 + 1];
        float sum_exm = stats[b * 8 + 2];
        float smax = stats[b * 8 + 3];
        float mg = ms[0], sg = ss[0];
        float mc = logf(EPSC * total + (1.0f - EPSC) * smax) + cmax;
        float M = fmaxf(mg, mc);
        float A = expf(cmax - M);
        float S = sg * expf(mg - M)
                + A * (EPSC * total * (float)VT_DIM + (1.0f - EPSC) * sum_exm);
        stats[b * 8 + 4] = M;
        stats[b * 8 + 5] = S;
        stats[b * 8 + 6] = A;
    }
}

__global__ void k_final(const float* __restrict__ gen, const float* __restrict__ projb,
                        const float* __restrict__ scat, const float* __restrict__ stats,
                        float* __restrict__ out)
{
    int i = blockIdx.x * blockDim.x + threadIdx.x;
    if (i >= B_DIM * VT_DIM) return;
    int b = i / VT_DIM;
    int j = i % VT_DIM;
    float M = stats[b * 8 + 4];
    float S = stats[b * 8 + 5];
    float A = stats[b * 8 + 6];
    float total = stats[b * 8 + 1];
    float val = A * (EPSC * total + (1.0f - EPSC) * scat[i]) / S;
    if (j < V_DIM)
        val += expf(gen[(size_t)b * V_DIM + j] + projb[j] - M) / S;
    out[2 * B_DIM * H_DIM + i] = val;
}

// ================= host launcher =================
extern "C" void kernel_launch(void* const* d_in, const int* in_sizes, int n_in,
                              void* d_out, int out_size)
{
    const float* u_enc  = (const float*)d_in[0];
    const int*   z_tm1  = (const int*)  d_in[1];
    const float* h0     = (const float*)d_in[2];
    const int*   u_inp  = (const int*)  d_in[3];
    const float* emb    = (const float*)d_in[4];
    const float* attn_W = (const float*)d_in[5];
    const float* attn_b = (const float*)d_in[6];
    const float* attn_v = (const float*)d_in[7];
    const float* gWih   = (const float*)d_in[8];
    const float* gWhh   = (const float*)d_in[9];
    const float* gbih   = (const float*)d_in[10];
    const float* gbhh   = (const float*)d_in[11];
    const float* projW  = (const float*)d_in[12];
    const float* projb  = (const float*)d_in[13];
    const float* c1W    = (const float*)d_in[14];
    const float* c1b    = (const float*)d_in[15];
    float* out = (float*)d_out;

    float* base = nullptr;
    cudaGetSymbolAddress((void**)&base, g_scratch);
    float* energy = base + OFF_ENERGY;
    float* hW1    = base + OFF_HW1;
    float* score  = base + OFF_SCORE;
    float* ctx    = base + OFF_CTX;
    float* x      = base + OFF_X;
    float* gi     = base + OFF_GI;
    float* gh     = base + OFF_GH;
    float* hnew   = base + OFF_HNEW;
    float* xp     = base + OFF_XP;
    float* gen    = base + OFF_GEN;
    float* raw    = base + OFF_RAW;
    float* scat   = base + OFF_SCAT;
    float* stats  = base + OFF_STATS;

    static bool attr_set = false;
    if (!attr_set) {
        cudaFuncSetAttribute(tgemm, cudaFuncAttributeMaxDynamicSharedMemorySize, TG_SMEM);
        attr_set = true;
    }

    const int MROWS = T_DIM * B_DIM;  // 8192

    // 0) zero the dense scatter buffer
    k_zero<<<512, 256>>>(scat, B_DIM * VT_DIM);

    // 1) hW1 = h0 @ W1^T   (W1 = attn_W[:, :H], stride 2H)
    tgemm<<<dim3(H_DIM / 128, 1), 256, TG_SMEM>>>(
        h0, attn_W, hW1, B_DIM, B_DIM, H_DIM, H_DIM, 2 * H_DIM, H_DIM);

    // 2) energy_pre = enc_rows @ W2^T  (W2 = attn_W[:, H:])
    tgemm<<<dim3(H_DIM / 128, MROWS / 128), 256, TG_SMEM>>>(
        u_enc, attn_W + H_DIM, energy, MROWS, MROWS, H_DIM, H_DIM, 2 * H_DIM, H_DIM);

    // 3) attention score, softmax, context
    k_score<<<MROWS / 8, 256>>>(energy, hW1, attn_b, attn_v, score);
    k_alpha<<<B_DIM, T_DIM>>>(score);
    k_ctx<<<B_DIM, H_DIM>>>(score, u_enc, ctx);

    // 4) GRU
    k_build_x<<<(B_DIM * (E_DIM + H_DIM) + 255) / 256, 256>>>(z_tm1, emb, ctx, x);
    tgemm<<<dim3(3 * H_DIM / 128, 1), 256, TG_SMEM>>>(
        x, gWih, gi, B_DIM, B_DIM, E_DIM + H_DIM, E_DIM + H_DIM, E_DIM + H_DIM, 3 * H_DIM);
    tgemm<<<dim3(3 * H_DIM / 128, 1), 256, TG_SMEM>>>(
        h0, gWhh, gh, B_DIM, B_DIM, H_DIM, H_DIM, H_DIM, 3 * H_DIM);
    k_gru<<<B_DIM, H_DIM>>>(gi, gh, gbih, gbhh, h0, ctx, hnew, xp, out);

    // 5) gen_score = [h_new, ctx] @ proj_W^T
    tgemm<<<dim3(V_DIM / 128, 1), 256, TG_SMEM>>>(
        xp, projW, gen, B_DIM, B_DIM, 2 * H_DIM, 2 * H_DIM, 2 * H_DIM, V_DIM);

    // 6) copy path: encC = enc_rows @ copy1_W^T (reuse energy scratch)
    tgemm<<<dim3(H_DIM / 128, MROWS / 128), 256, TG_SMEM>>>(
        u_enc, c1W, energy, MROWS, MROWS, H_DIM, H_DIM, H_DIM, H_DIM);
    k_raw<<<MROWS / 8, 256>>>(energy, c1b, hnew, raw);

    // 7) copy log-score stats + deterministic scatter
    k_copystats<<<B_DIM, T_DIM>>>(raw, u_inp, scat, stats);

    // 8) global softmax reduction (u_copy folded analytically)
    k_reduce<<<B_DIM, 256>>>(gen, projb, stats);

    // 9) final proba
    k_final<<<(B_DIM * VT_DIM + 255) / 256, 256>>>(gen, projb, scat, stats, out);
}

// round 4
// speedup vs baseline: 3.3246x; 1.1751x over previous
#include <cuda_runtime.h>
#include <cuda_bf16.h>
#include <math.h>
#include <stdint.h>

// Problem constants
#define T_DIM 128
#define B_DIM 64
#define H_DIM 512
#define E_DIM 256
#define V_DIM 32000
#define VT_DIM (V_DIM + T_DIM)   // 32128
#define EPSC 1e-10f

// ---------------- scratch ----------------
static constexpr size_t OFF_SPART  = 0;                                   // 4 x B*T score partials
static constexpr size_t OFF_RPART  = OFF_SPART + 4 * (size_t)B_DIM * T_DIM;
static constexpr size_t OFF_HW1    = OFF_RPART + 4 * (size_t)B_DIM * T_DIM;
static constexpr size_t OFF_SCORE  = OFF_HW1   + (size_t)B_DIM * H_DIM;
static constexpr size_t OFF_CTX    = OFF_SCORE + (size_t)B_DIM * T_DIM;
static constexpr size_t OFF_X      = OFF_CTX   + (size_t)B_DIM * H_DIM;
static constexpr size_t OFF_GI     = OFF_X     + (size_t)B_DIM * (E_DIM + H_DIM);
static constexpr size_t OFF_GH     = OFF_GI    + (size_t)B_DIM * 3 * H_DIM;
static constexpr size_t OFF_HNEW   = OFF_GH    + (size_t)B_DIM * 3 * H_DIM;
static constexpr size_t OFF_XP     = OFF_HNEW  + (size_t)B_DIM * H_DIM;
static constexpr size_t OFF_GEN    = OFF_XP    + (size_t)B_DIM * 2 * H_DIM;
static constexpr size_t OFF_RAW    = OFF_GEN   + (size_t)B_DIM * V_DIM;
static constexpr size_t OFF_SCAT   = OFF_RAW   + (size_t)B_DIM * T_DIM;
static constexpr size_t OFF_STATS  = OFF_SCAT  + (size_t)B_DIM * VT_DIM;
static constexpr size_t SCRATCH_TOTAL = OFF_STATS + (size_t)B_DIM * 8;

__device__ __align__(16) float g_scratch[SCRATCH_TOTAL];

// ================= warp MMA helpers (baseline PTX, sm_80+) ====
__device__ __forceinline__ uint32_t smem_u32(const void* p) {
    uint32_t a;
    asm("{ .reg .u64 t; cvta.to.shared.u64 t, %1; cvt.u32.u64 %0, t; }" : "=r"(a) : "l"(p));
    return a;
}
__device__ __forceinline__ void ldsm4(uint32_t* r, uint32_t addr) {
    asm volatile("ldmatrix.sync.aligned.m8n8.x4.shared.b16 {%0,%1,%2,%3}, [%4];"
        : "=r"(r[0]), "=r"(r[1]), "=r"(r[2]), "=r"(r[3]) : "r"(addr));
}
__device__ __forceinline__ void mma_bf16(float* c, const uint32_t* a, const uint32_t* b) {
    asm volatile("mma.sync.aligned.m16n8k16.row.col.f32.bf16.bf16.f32 "
        "{%0,%1,%2,%3}, {%4,%5,%6,%7}, {%8,%9}, {%0,%1,%2,%3};"
        : "+f"(c[0]), "+f"(c[1]), "+f"(c[2]), "+f"(c[3])
        : "r"(a[0]), "r"(a[1]), "r"(a[2]), "r"(a[3]), "r"(b[0]), "r"(b[1]));
}
__device__ __forceinline__ void cvt_split(float4 v, uint2& hi, uint2& lo) {
    uint32_t h01, h23;
    asm("cvt.rn.bf16x2.f32 %0, %1, %2;" : "=r"(h01) : "f"(v.y), "f"(v.x));
    asm("cvt.rn.bf16x2.f32 %0, %1, %2;" : "=r"(h23) : "f"(v.w), "f"(v.z));
    float h0 = __uint_as_float(h01 << 16);
    float h1 = __uint_as_float(h01 & 0xffff0000u);
    float h2 = __uint_as_float(h23 << 16);
    float h3 = __uint_as_float(h23 & 0xffff0000u);
    uint32_t l01, l23;
    asm("cvt.rn.bf16x2.f32 %0, %1, %2;" : "=r"(l01) : "f"(v.y - h1), "f"(v.x - h0));
    asm("cvt.rn.bf16x2.f32 %0, %1, %2;" : "=r"(l23) : "f"(v.w - h3), "f"(v.z - h2));
    hi = make_uint2(h01, h23);
    lo = make_uint2(l01, l23);
}

// ================= tensor-core GEMM (HMMA, bf16x3 split) =================
// C[m,n] = sum_k A[m,k] * B[n,k]; fp32 in/out. CTA tile (32*MT) x 128, BK=32, 256 thr.
// If red_out != null: fused epilogue
//   red[m] = sum_n wgt(n, b) * tanh(acc[m,n] + add_bh[b, n] + bias_n[n]),  b = m & 63
//   written as partial to red_out[blockIdx.x][b*T + t], t = m >> 6.
static constexpr int ROWB = 80;                 // bytes per smem row (32 bf16 + pad)

template<int MT>
__global__ void __launch_bounds__(256, 1) tgemm(
    const float* __restrict__ A, const float* __restrict__ B, float* __restrict__ C,
    int M_A, int M_C, int K, int lda, int ldb, int ldc,
    const float* __restrict__ add_bh, const float* __restrict__ bias_n,
    const float* __restrict__ wgt_n,  const float* __restrict__ wgt_bh,
    float* __restrict__ red_out)
{
    constexpr int ROWS   = 32 * MT;           // CTA M rows
    constexpr int TILEA  = ROWS * ROWB;
    constexpr int TILEB  = 128 * ROWB;
    constexpr int STAGEB = 2 * TILEA + 2 * TILEB;

    extern __shared__ char smem[];
    const uint32_t sb = smem_u32(smem);
    const int tid  = threadIdx.x;
    const int lane = tid & 31;
    const int warp = tid >> 5;
    const int wy   = warp >> 2;      // 0..1
    const int wx   = warp & 3;       // 0..3
    const int m0   = blockIdx.y * ROWS;
    const int n0   = blockIdx.x * 128;

    float acc[MT][4][4];
#pragma unroll
    for (int i = 0; i < MT; i++)
#pragma unroll
        for (int j = 0; j < 4; j++)
#pragma unroll
            for (int q = 0; q < 4; q++) acc[i][j][q] = 0.0f;

    const int nchunk = K >> 5;
    float4 ra[MT], rb[4];

    auto load_regs = [&](int c) {
        const int k0 = c << 5;
#pragma unroll
        for (int i = 0; i < MT; i++) {
            int id  = tid + (i << 8);
            int row = id >> 3;
            int kq  = id & 7;
            ra[i] = (m0 + row < M_A)
                  ? *(const float4*)&A[(size_t)(m0 + row) * lda + k0 + (kq << 2)]
                  : make_float4(0.f, 0.f, 0.f, 0.f);
        }
#pragma unroll
        for (int i = 0; i < 4; i++) {
            int id  = tid + (i << 8);
            int row = id >> 3;
            int kq  = id & 7;
            rb[i] = *(const float4*)&B[(size_t)(n0 + row) * ldb + k0 + (kq << 2)];
        }
    };
    auto store_smem = [&](int stage) {
        char* base = smem + stage * STAGEB;
        uint2 hi, lo;
#pragma unroll
        for (int i = 0; i < MT; i++) {
            int id  = tid + (i << 8);
            int row = id >> 3;
            int kq  = id & 7;
            int off = row * ROWB + (kq << 3);
            cvt_split(ra[i], hi, lo);
            *(uint2*)(base + off)         = hi;           // A_hi
            *(uint2*)(base + TILEA + off) = lo;           // A_lo
        }
#pragma unroll
        for (int i = 0; i < 4; i++) {
            int id  = tid + (i << 8);
            int row = id >> 3;
            int kq  = id & 7;
            int off = row * ROWB + (kq << 3);
            cvt_split(rb[i], hi, lo);
            *(uint2*)(base + 2 * TILEA + off)         = hi; // B_hi
            *(uint2*)(base + 2 * TILEA + TILEB + off) = lo; // B_lo
        }
    };
    auto compute = [&](int stage) {
        const uint32_t s0 = sb + stage * STAGEB;
        const int q = lane >> 3, r = lane & 7;
#pragma unroll
        for (int ks = 0; ks < 32; ks += 16) {
            uint32_t a_hi[MT][4], a_lo[MT][4], b_hi[4][2], b_lo[4][2];
            {
                int arow = wy * (MT * 16) + ((q & 1) ? 8 : 0) + r;
                int acol = ks + ((q & 2) ? 8 : 0);
                uint32_t addr = s0 + arow * ROWB + acol * 2;
#pragma unroll
                for (int mt = 0; mt < MT; mt++) {
                    ldsm4(a_hi[mt], addr + mt * (16 * ROWB));
                    ldsm4(a_lo[mt], addr + TILEA + mt * (16 * ROWB));
                }
            }
            {
                int brow = wx * 32 + ((q & 2) ? 8 : 0) + r;
                int bcol = ks + ((q & 1) ? 8 : 0);
                uint32_t addr = s0 + 2 * TILEA + brow * ROWB + bcol * 2;
#pragma unroll
                for (int np = 0; np < 2; np++) {
                    ldsm4(&b_hi[np * 2][0], addr + np * (16 * ROWB));
                    ldsm4(&b_lo[np * 2][0], addr + TILEB + np * (16 * ROWB));
                }
            }
#pragma unroll
            for (int mt = 0; mt < MT; mt++)
#pragma unroll
                for (int nt = 0; nt < 4; nt++) {
                    mma_bf16(acc[mt][nt], a_hi[mt], b_hi[nt]);
                    mma_bf16(acc[mt][nt], a_hi[mt], b_lo[nt]);
                    mma_bf16(acc[mt][nt], a_lo[mt], b_hi[nt]);
                }
        }
    };

    // pipelined main loop
    load_regs(0);
    store_smem(0);
    if (nchunk > 1) load_regs(1);
    __syncthreads();
    for (int c = 0; c < nchunk; c++) {
        if (c + 1 < nchunk) store_smem((c + 1) & 1);
        if (c + 2 < nchunk) load_regs(c + 2);
        compute(c & 1);
        __syncthreads();
    }

    const int g = lane >> 2, tig = lane & 3;

    if (red_out) {
        // fused tanh-weighted row reduction
        float* red = (float*)smem;   // [4][ROWS], safe: synced above
#pragma unroll
        for (int mt = 0; mt < MT; mt++) {
            int rl0 = wy * (MT * 16) + mt * 16 + g;
            int rl1 = rl0 + 8;
            int b0 = (m0 + rl0) & 63, b1 = (m0 + rl1) & 63;
            float p0 = 0.f, p1 = 0.f;
#pragma unroll
            for (int nt = 0; nt < 4; nt++) {
                int col = n0 + wx * 32 + nt * 8 + tig * 2;
#pragma unroll
                for (int cc = 0; cc < 2; cc++) {
                    int cg = col + cc;
                    float bias = bias_n[cg];
                    float a0 = add_bh ? add_bh[(size_t)b0 * H_DIM + cg] : 0.f;
                    float a1 = add_bh ? add_bh[(size_t)b1 * H_DIM + cg] : 0.f;
                    float w0 = wgt_n ? wgt_n[cg] : wgt_bh[(size_t)b0 * H_DIM + cg];
                    float w1 = wgt_n ? wgt_n[cg] : wgt_bh[(size_t)b1 * H_DIM + cg];
                    p0 += w0 * tanhf(acc[mt][nt][cc]     + a0 + bias);
                    p1 += w1 * tanhf(acc[mt][nt][2 + cc] + a1 + bias);
                }
            }
            p0 += __shfl_xor_sync(0xffffffffu, p0, 1);
            p0 += __shfl_xor_sync(0xffffffffu, p0, 2);
            p1 += __shfl_xor_sync(0xffffffffu, p1, 1);
            p1 += __shfl_xor_sync(0xffffffffu, p1, 2);
            if (tig == 0) { red[wx * ROWS + rl0] = p0; red[wx * ROWS + rl1] = p1; }
        }
        __syncthreads();
        for (int r = tid; r < ROWS; r += 256) {
            float s = red[r] + red[ROWS + r] + red[2 * ROWS + r] + red[3 * ROWS + r];
            int m = m0 + r;
            red_out[(size_t)blockIdx.x * (B_DIM * T_DIM) + (m & 63) * T_DIM + (m >> 6)] = s;
        }
        return;
    }

    // plain store epilogue
#pragma unroll
    for (int mt = 0; mt < MT; mt++) {
        int row0 = m0 + wy * (MT * 16) + mt * 16 + g;
#pragma unroll
        for (int nt = 0; nt < 4; nt++) {
            int col = n0 + wx * 32 + nt * 8 + tig * 2;
            if (row0 < M_C) {
                *(float2*)&C[(size_t)row0 * ldc + col] = make_float2(acc[mt][nt][0], acc[mt][nt][1]);
                *(float2*)&C[(size_t)(row0 + 8) * ldc + col] = make_float2(acc[mt][nt][2], acc[mt][nt][3]);
            }
        }
    }
}

static constexpr int SMEM_MT4 = 2 * (2 * 128 * ROWB + 2 * 128 * ROWB);  // 81920
static constexpr int SMEM_MT2 = 2 * (2 * 64  * ROWB + 2 * 128 * ROWB);  // 61440

// ================= elementwise / reduction kernels =================

__global__ void k_zero(float* p, int n)
{
    for (int i = blockIdx.x * blockDim.x + threadIdx.x; i < n; i += gridDim.x * blockDim.x)
        p[i] = 0.0f;
}

// softmax over t per b; input = sum of 4 partials
__global__ void k_alpha(const float* __restrict__ part, float* __restrict__ alpha)
{
    int b = blockIdx.x, t = threadIdx.x;
    int idx = b * T_DIM + t;
    __shared__ float sm[T_DIM];
    float v = part[idx] + part[B_DIM * T_DIM + idx]
            + part[2 * B_DIM * T_DIM + idx] + part[3 * B_DIM * T_DIM + idx];
    sm[t] = v; __syncthreads();
    for (int o = 64; o > 0; o >>= 1) { if (t < o) sm[t] = fmaxf(sm[t], sm[t + o]); __syncthreads(); }
    float mx = sm[0]; __syncthreads();
    float e = expf(v - mx);
    sm[t] = e; __syncthreads();
    for (int o = 64; o > 0; o >>= 1) { if (t < o) sm[t] += sm[t + o]; __syncthreads(); }
    alpha[idx] = e / sm[0];
}

// ctx[b,h] = sum_t alpha[b,t] * enc[t,b,h]; grid (B, H/128), 128 thr
__global__ void k_ctx(const float* __restrict__ alpha, const float* __restrict__ enc,
                      float* __restrict__ ctx)
{
    int b = blockIdx.x;
    int h = blockIdx.y * 128 + threadIdx.x;
    __shared__ float al[T_DIM];
    if (threadIdx.x < T_DIM) al[threadIdx.x] = alpha[b * T_DIM + threadIdx.x];
    __syncthreads();
    float acc = 0.0f;
#pragma unroll 4
    for (int t = 0; t < T_DIM; t++)
        acc += al[t] * enc[((size_t)t * B_DIM + b) * H_DIM + h];
    ctx[b * H_DIM + h] = acc;
}

__global__ void k_build_x(const int* __restrict__ z, const float* __restrict__ emb,
                          const float* __restrict__ ctx, float* __restrict__ x)
{
    int i = blockIdx.x * blockDim.x + threadIdx.x;
    if (i >= B_DIM * (E_DIM + H_DIM)) return;
    int b = i / (E_DIM + H_DIM);
    int c = i % (E_DIM + H_DIM);
    x[i] = (c < E_DIM) ? emb[(size_t)z[b] * E_DIM + c] : ctx[b * H_DIM + (c - E_DIM)];
}

__global__ void k_gru(const float* __restrict__ gi, const float* __restrict__ gh,
                      const float* __restrict__ bih, const float* __restrict__ bhh,
                      const float* __restrict__ h_prev, const float* __restrict__ ctx,
                      float* __restrict__ hnew, float* __restrict__ xp,
                      float* __restrict__ out)
{
    int b = blockIdx.x, h = threadIdx.x;
    const float* gib = gi + (size_t)b * 3 * H_DIM;
    const float* ghb = gh + (size_t)b * 3 * H_DIM;
    float ir  = gib[h]              + bih[h];
    float iz  = gib[H_DIM + h]      + bih[H_DIM + h];
    float in_ = gib[2 * H_DIM + h]  + bih[2 * H_DIM + h];
    float hr  = ghb[h]              + bhh[h];
    float hz  = ghb[H_DIM + h]      + bhh[H_DIM + h];
    float hn  = ghb[2 * H_DIM + h]  + bhh[2 * H_DIM + h];
    float r  = 1.0f / (1.0f + expf(-(ir + hr)));
    float zz = 1.0f / (1.0f + expf(-(iz + hz)));
    float n  = tanhf(in_ + r * hn);
    float hp = h_prev[b * H_DIM + h];
    float v  = (1.0f - zz) * n + zz * hp;
    hnew[b * H_DIM + h] = v;
    out[b * H_DIM + h] = v;
    out[B_DIM * H_DIM + b * H_DIM + h] = v;
    xp[b * 2 * H_DIM + h] = v;
    xp[b * 2 * H_DIM + H_DIM + h] = ctx[b * H_DIM + h];
}

// stats + parallel deterministic scatter; raw = sum of 4 partials
__global__ void k_copystats(const float* __restrict__ rpart, const int* __restrict__ u_input,
                            float* __restrict__ scat, float* __restrict__ stats)
{
    int b = blockIdx.x, t = threadIdx.x;
    int idx0 = b * T_DIM + t;
    __shared__ float sm[T_DIM];
    __shared__ float exm[T_DIM];
    __shared__ int   sidx[T_DIM];
    float v = rpart[idx0] + rpart[B_DIM * T_DIM + idx0]
            + rpart[2 * B_DIM * T_DIM + idx0] + rpart[3 * B_DIM * T_DIM + idx0];
    sm[t] = v; __syncthreads();
    for (int o = 64; o > 0; o >>= 1) { if (t < o) sm[t] = fmaxf(sm[t], sm[t + o]); __syncthreads(); }
    float cmax = sm[0]; __syncthreads();

    float e = expf(v - cmax);
    int tok = u_input[t * B_DIM + b];
    sidx[t] = (tok == 2) ? (V_DIM + t) : tok;
    float em = (tok != 0) ? e : 0.0f;
    exm[t] = em;

    sm[t] = e; __syncthreads();
    for (int o = 64; o > 0; o >>= 1) { if (t < o) sm[t] += sm[t + o]; __syncthreads(); }
    float total = sm[0]; __syncthreads();

    sm[t] = em; __syncthreads();
    for (int o = 64; o > 0; o >>= 1) { if (t < o) sm[t] += sm[t + o]; __syncthreads(); }
    float sum_exm = sm[0]; __syncthreads();

    int idx = sidx[t];
    bool first = true;
    for (int i = 0; i < t; i++) if (sidx[i] == idx) { first = false; break; }
    float a = 0.0f;
    if (first) {
        for (int i = t; i < T_DIM; i++) if (sidx[i] == idx) a += exm[i];
        scat[(size_t)b * VT_DIM + idx] = a;
    }
    sm[t] = a; __syncthreads();
    for (int o = 64; o > 0; o >>= 1) { if (t < o) sm[t] = fmaxf(sm[t], sm[t + o]); __syncthreads(); }
    if (t == 0) {
        stats[b * 8 + 0] = cmax;
        stats[b * 8 + 1] = total;
        stats[b * 8 + 2] = sum_exm;
        stats[b * 8 + 3] = sm[0];
    }
}

__global__ void k_reduce(const float* __restrict__ gen, const float* __restrict__ projb,
                         float* __restrict__ stats)
{
    int b = blockIdx.x, tid = threadIdx.x;
    float m = -1e30f, s = 0.0f;
    for (int v = tid; v < V_DIM; v += 512) {
        float l = gen[(size_t)b * V_DIM + v] + projb[v];
        float mn = fmaxf(m, l);
        s = s * expf(m - mn) + expf(l - mn);
        m = mn;
    }
    __shared__ float ms[512], ss[512];
    ms[tid] = m; ss[tid] = s; __syncthreads();
    for (int o = 256; o > 0; o >>= 1) {
        if (tid < o) {
            float m2 = ms[tid + o], s2 = ss[tid + o];
            float mn = fmaxf(ms[tid], m2);
            ss[tid] = ss[tid] * expf(ms[tid] - mn) + s2 * expf(m2 - mn);
            ms[tid] = mn;
        }
        __syncthreads();
    }
    if (tid == 0) {
        float cmax = stats[b * 8 + 0];
        float total = stats[b * 8 + 1];
        float sum_exm = stats[b * 8 + 2];
        float smax = stats[b * 8 + 3];
        float mg = ms[0], sg = ss[0];
        float mc = logf(EPSC * total + (1.0f - EPSC) * smax) + cmax;
        float M = fmaxf(mg, mc);
        float A = expf(cmax - M);
        float S = sg * expf(mg - M)
                + A * (EPSC * total * (float)VT_DIM + (1.0f - EPSC) * sum_exm);
        stats[b * 8 + 4] = M;
        stats[b * 8 + 5] = S;
        stats[b * 8 + 6] = A;
    }
}

__global__ void k_final(const float* __restrict__ gen, const float* __restrict__ projb,
                        const float* __restrict__ scat, const float* __restrict__ stats,
                        float* __restrict__ out)
{
    int i = blockIdx.x * blockDim.x + threadIdx.x;
    if (i >= B_DIM * VT_DIM) return;
    int b = i / VT_DIM;
    int j = i % VT_DIM;
    float M = stats[b * 8 + 4];
    float S = stats[b * 8 + 5];
    float A = stats[b * 8 + 6];
    float total = stats[b * 8 + 1];
    float val = A * (EPSC * total + (1.0f - EPSC) * scat[i]) / S;
    if (j < V_DIM)
        val += expf(gen[(size_t)b * V_DIM + j] + projb[j] - M) / S;
    out[2 * B_DIM * H_DIM + i] = val;
}

// ================= host launcher =================
extern "C" void kernel_launch(void* const* d_in, const int* in_sizes, int n_in,
                              void* d_out, int out_size)
{
    const float* u_enc  = (const float*)d_in[0];
    const int*   z_tm1  = (const int*)  d_in[1];
    const float* h0     = (const float*)d_in[2];
    const int*   u_inp  = (const int*)  d_in[3];
    const float* emb    = (const float*)d_in[4];
    const float* attn_W = (const float*)d_in[5];
    const float* attn_b = (const float*)d_in[6];
    const float* attn_v = (const float*)d_in[7];
    const float* gWih   = (const float*)d_in[8];
    const float* gWhh   = (const float*)d_in[9];
    const float* gbih   = (const float*)d_in[10];
    const float* gbhh   = (const float*)d_in[11];
    const float* projW  = (const float*)d_in[12];
    const float* projb  = (const float*)d_in[13];
    const float* c1W    = (const float*)d_in[14];
    const float* c1b    = (const float*)d_in[15];
    float* out = (float*)d_out;

    float* base = nullptr;
    cudaGetSymbolAddress((void**)&base, g_scratch);
    float* spart  = base + OFF_SPART;
    float* rpart  = base + OFF_RPART;
    float* hW1    = base + OFF_HW1;
    float* score  = base + OFF_SCORE;
    float* ctx    = base + OFF_CTX;
    float* x      = base + OFF_X;
    float* gi     = base + OFF_GI;
    float* gh     = base + OFF_GH;
    float* hnew   = base + OFF_HNEW;
    float* xp     = base + OFF_XP;
    float* gen    = base + OFF_GEN;
    float* scat   = base + OFF_SCAT;
    float* stats  = base + OFF_STATS;

    cudaFuncSetAttribute(tgemm<4>, cudaFuncAttributeMaxDynamicSharedMemorySize, SMEM_MT4);
    cudaFuncSetAttribute(tgemm<2>, cudaFuncAttributeMaxDynamicSharedMemorySize, SMEM_MT2);

    const int MROWS = T_DIM * B_DIM;  // 8192

    // 0) zero the dense scatter buffer
    k_zero<<<512, 256>>>(scat, B_DIM * VT_DIM);

    // 1) hW1 = h0 @ W1^T
    tgemm<2><<<dim3(H_DIM / 128, 1), 256, SMEM_MT2>>>(
        h0, attn_W, hW1, B_DIM, B_DIM, H_DIM, H_DIM, 2 * H_DIM, H_DIM,
        nullptr, nullptr, nullptr, nullptr, nullptr);

    // 2) energy GEMM with fused score reduction -> spart[4][B*T]
    tgemm<4><<<dim3(H_DIM / 128, MROWS / 128), 256, SMEM_MT4>>>(
        u_enc, attn_W + H_DIM, nullptr, MROWS, 0, H_DIM, H_DIM, 2 * H_DIM, 0,
        hW1, attn_b, attn_v, nullptr, spart);

    // 3) alpha softmax (sums partials), context
    k_alpha<<<B_DIM, T_DIM>>>(spart, score);
    k_ctx<<<dim3(B_DIM, H_DIM / 128), 128>>>(score, u_enc, ctx);

    // 4) GRU
    k_build_x<<<(B_DIM * (E_DIM + H_DIM) + 255) / 256, 256>>>(z_tm1, emb, ctx, x);
    tgemm<2><<<dim3(3 * H_DIM / 128, 1), 256, SMEM_MT2>>>(
        x, gWih, gi, B_DIM, B_DIM, E_DIM + H_DIM, E_DIM + H_DIM, E_DIM + H_DIM, 3 * H_DIM,
        nullptr, nullptr, nullptr, nullptr, nullptr);
    tgemm<2><<<dim3(3 * H_DIM / 128, 1), 256, SMEM_MT2>>>(
        h0, gWhh, gh, B_DIM, B_DIM, H_DIM, H_DIM, H_DIM, 3 * H_DIM,
        nullptr, nullptr, nullptr, nullptr, nullptr);
    k_gru<<<B_DIM, H_DIM>>>(gi, gh, gbih, gbhh, h0, ctx, hnew, xp, out);

    // 5) copy GEMM with fused raw reduction -> rpart[4][B*T]
    tgemm<4><<<dim3(H_DIM / 128, MROWS / 128), 256, SMEM_MT4>>>(
        u_enc, c1W, nullptr, MROWS, 0, H_DIM, H_DIM, H_DIM, 0,
        nullptr, c1b, nullptr, hnew, rpart);
    k_copystats<<<B_DIM, T_DIM>>>(rpart, u_inp, scat, stats);

    // 6) gen_score = [h_new, ctx] @ proj_W^T  (M=64 tile, no padding waste)
    tgemm<2><<<dim3(V_DIM / 128, 1), 256, SMEM_MT2>>>(
        xp, projW, gen, B_DIM, B_DIM, 2 * H_DIM, 2 * H_DIM, 2 * H_DIM, V_DIM,
        nullptr, nullptr, nullptr, nullptr, nullptr);

    // 7) global softmax reduction + final proba
    k_reduce<<<B_DIM, 512>>>(gen, projb, stats);
    k_final<<<(B_DIM * VT_DIM + 255) / 256, 256>>>(gen, projb, scat, stats, out);
}